// round 9
// baseline (speedup 1.0000x reference)
#include <cuda_runtime.h>
#include <cstdint>

// Shape fixed by dataset: (64, 68, 128, 128) fp32 x2.
static constexpr int IMG_ROWS    = 128;
static constexpr int TOTAL_PAIRS = 64 * 68 * (IMG_ROWS / 2);  // 278528 row-pairs
static constexpr int WARPS       = 8;
static constexpr int NBLK        = 148 * 7;             // 1036: one wave at 7 blocks/SM
static constexpr int NWARPS      = NBLK * WARPS;        // 8288 grid-stride warps
static constexpr double TOTAL_ELEMS = 71303168.0;

__device__ double       g_part[NBLK];
__device__ unsigned int g_count = 0;             // self-resetting each launch

__device__ __forceinline__ float ex2a(float x) {
    float y; asm("ex2.approx.f32 %0, %1;" : "=f"(y) : "f"(x)); return y;
}
__device__ __forceinline__ float lg2a(float x) {
    float y; asm("lg2.approx.f32 %0, %1;" : "=f"(y) : "f"(x)); return y;
}

__device__ __forceinline__ float4 max4(float4 a, float4 b) {
    return make_float4(fmaxf(a.x, b.x), fmaxf(a.y, b.y),
                       fmaxf(a.z, b.z), fmaxf(a.w, b.w));
}

// Horizontal 3-max with SAME padding (edge lanes use clipped window).
__device__ __forceinline__ float4 hmax3(float4 v, bool la0, bool la31) {
    float left  = __shfl_up_sync(0xffffffffu, v.w, 1);
    float right = __shfl_down_sync(0xffffffffu, v.x, 1);
    float m01 = fmaxf(v.x, v.y);
    float m12 = fmaxf(v.y, v.z);
    float m23 = fmaxf(v.z, v.w);
    float4 h;
    h.x = la0  ? m01 : fmaxf(left, m01);
    h.y = fmaxf(v.x, m12);
    h.z = fmaxf(v.y, m23);
    h.w = la31 ? m23 : fmaxf(m23, right);
    return h;
}

// Exact rewrite of reference (scaled by 1/14, x14 applied at warp level):
//   loss14 = ln(1+s) + [2*asl*s/(1+s)] * relu
//   s = min(d,0.5)^asl, relu = d - min(d,0.5), asl = 2.1 - l
//   2/(1+s) ~= 1.4815*(1-z)(1+z^2), z = (1+s)/1.35 - 1  (rel err <= 5.6e-5 on
//   the relu-active range s in (0.233,0.467); elsewhere relu == 0).
//   (R8 showed MUFU rcp here regresses: 4th MUFU + serial dependency. Series
//   ops are independent FMA-pipe work that overlaps; keep the series.)
//   mask: 255*max3x3(l) >= 25.5  <=>  max3x3(l) >= 0.1
__device__ __forceinline__ void elem(float p, float l, float vm,
                                     float& acc, float& accm) {
    float d    = fabsf(p - l);
    float m    = fminf(d, 0.5f);
    float relu = d - m;
    float asl  = 2.1f - l;
    float s    = ex2a(asl * lg2a(m));
    float u    = 1.0f + s;
    float la   = 0.6931471805599453f * lg2a(u);            // ln(1+s)
    float z    = fmaf(u, 0.7407407407407407f, -1.0f);
    float h    = fmaf(z, -1.4814814814814814f, 1.4814814814814814f);
    float t    = fmaf(z * z, h, h);                        // ~= 2/(1+s)
    float loss = fmaf((asl * s) * t, relu, la);
    acc += loss;
    if (vm >= 0.1f) accm += loss;
}

// Grid-stride over row PAIRS (r, r+1 within one image). 3x3 max is separable;
// the shared middle term max(l[r], l[r+1]) serves both rows' vertical maxes.
// 6 float4 loads per 2 rows; neighbor re-reads hit L2/L1.
__global__ void __launch_bounds__(256, 7)
awing(const float* __restrict__ pred, const float* __restrict__ lmk,
      float* __restrict__ out) {
    const int  lane = threadIdx.x & 31;
    const int  wid  = threadIdx.x >> 5;
    const int  gw   = blockIdx.x * WARPS + wid;
    const bool la0  = (lane == 0), la31 = (lane == 31);

    const float4* lp4 = reinterpret_cast<const float4*>(lmk);
    const float4* pp4 = reinterpret_cast<const float4*>(pred);

    float acc = 0.0f, accm = 0.0f;

#pragma unroll 1
    for (int pair = gw; pair < TOTAL_PAIRS; pair += NWARPS) {
        const int r  = (pair & 63) * 2;             // even row within image
        const int f0 = pair * 64 + lane;            // float4 idx of row r
        const int f1 = f0 + 32;                     // row r+1
        const int fu = (r == 0)   ? f0 : f0 - 32;   // row r-1 (SAME padding)
        const int fd = (r == 126) ? f1 : f1 + 32;   // row r+2 (SAME padding)

        float4 lu = lp4[fu];
        float4 l0 = lp4[f0];
        float4 l1 = lp4[f1];
        float4 ld = lp4[fd];
        float4 p0 = __ldcs(pp4 + f0);
        float4 p1 = __ldcs(pp4 + f1);

        float4 m01 = max4(l0, l1);                  // shared middle
        float4 ha  = hmax3(max4(lu, m01), la0, la31);   // 3x3 max, row r
        float4 hb  = hmax3(max4(m01, ld), la0, la31);   // 3x3 max, row r+1

        elem(p0.x, l0.x, ha.x, acc, accm);
        elem(p0.y, l0.y, ha.y, acc, accm);
        elem(p0.z, l0.z, ha.z, acc, accm);
        elem(p0.w, l0.w, ha.w, acc, accm);
        elem(p1.x, l1.x, hb.x, acc, accm);
        elem(p1.y, l1.y, hb.y, acc, accm);
        elem(p1.z, l1.z, hb.z, acc, accm);
        elem(p1.w, l1.w, hb.w, acc, accm);
    }

    float tot = fmaf(accm, 10.0f, acc) * 14.0f;
#pragma unroll
    for (int o = 16; o; o >>= 1)
        tot += __shfl_xor_sync(0xffffffffu, tot, o);

    __shared__ float  wsum[WARPS];
    __shared__ double sh[256];
    __shared__ bool   isLast;
    if (lane == 0) wsum[wid] = tot;
    __syncthreads();
    if (threadIdx.x == 0) {
        double s = 0.0;
#pragma unroll
        for (int i = 0; i < WARPS; ++i) s += (double)wsum[i];
        g_part[blockIdx.x] = s;
        __threadfence();
        unsigned int old = atomicAdd(&g_count, 1u);
        isLast = (old == (unsigned)(NBLK - 1));
        if (isLast) g_count = 0;             // reset for next graph replay
    }
    __syncthreads();

    if (isLast) {
        double s = 0.0;
        for (int i = threadIdx.x; i < NBLK; i += 256)
            s += __ldcg(&g_part[i]);
        sh[threadIdx.x] = s;
        __syncthreads();
#pragma unroll
        for (int k = 128; k; k >>= 1) {
            if (threadIdx.x < k) sh[threadIdx.x] += sh[threadIdx.x + k];
            __syncthreads();
        }
        if (threadIdx.x == 0)
            out[0] = (float)(sh[0] * (1.0 / TOTAL_ELEMS));
    }
}

extern "C" void kernel_launch(void* const* d_in, const int* in_sizes, int n_in,
                              void* d_out, int out_size) {
    const float* pred = (const float*)d_in[0];
    const float* lmk  = (const float*)d_in[1];
    awing<<<NBLK, 256>>>(pred, lmk, (float*)d_out);
}

// round 10
// speedup vs baseline: 1.3001x; 1.3001x over previous
#include <cuda_runtime.h>
#include <cstdint>

// Shape fixed by dataset: (64, 68, 128, 128) fp32 x2.
static constexpr int IMG_ROWS    = 128;
static constexpr int TOTAL_PAIRS = 64 * 68 * (IMG_ROWS / 2);  // 278528 row-pairs
static constexpr int WARPS       = 8;
static constexpr int NBLK        = 888;                 // 148 SMs x 6 blocks, one wave
static constexpr int NWARPS      = NBLK * WARPS;        // 7104 grid-stride warps
static constexpr double TOTAL_ELEMS = 71303168.0;

__device__ double       g_part[NBLK];
__device__ unsigned int g_count = 0;             // self-resetting each launch

__device__ __forceinline__ float ex2a(float x) {
    float y; asm("ex2.approx.f32 %0, %1;" : "=f"(y) : "f"(x)); return y;
}
__device__ __forceinline__ float lg2a(float x) {
    float y; asm("lg2.approx.f32 %0, %1;" : "=f"(y) : "f"(x)); return y;
}

__device__ __forceinline__ float4 max4(float4 a, float4 b) {
    return make_float4(fmaxf(a.x, b.x), fmaxf(a.y, b.y),
                       fmaxf(a.z, b.z), fmaxf(a.w, b.w));
}

// Horizontal 3-max with SAME padding (edge lanes use clipped window).
__device__ __forceinline__ float4 hmax3(float4 v, bool la0, bool la31) {
    float left  = __shfl_up_sync(0xffffffffu, v.w, 1);
    float right = __shfl_down_sync(0xffffffffu, v.x, 1);
    float m01 = fmaxf(v.x, v.y);
    float m12 = fmaxf(v.y, v.z);
    float m23 = fmaxf(v.z, v.w);
    float4 h;
    h.x = la0  ? m01 : fmaxf(left, m01);
    h.y = fmaxf(v.x, m12);
    h.z = fmaxf(v.y, m23);
    h.w = la31 ? m23 : fmaxf(m23, right);
    return h;
}

// Exact rewrite of reference (scaled by 1/14, x14 applied at warp level):
//   loss14 = ln(1+s) + [2*asl*s/(1+s)] * relu
//   s = min(d,0.5)^asl, relu = d - min(d,0.5), asl = 2.1 - l
//   2/(1+s) ~= 1.4815*(1-z)(1+z^2), z = (1+s)/1.35 - 1  (rel err <= 5.6e-5 on
//   the relu-active range s in (0.233,0.467); elsewhere relu == 0).
//   (R8: MUFU rcp here regresses — 4th MUFU + serial dependency; series ops
//   are independent FMA-pipe work that overlaps. Keep the series.)
//   mask: 255*max3x3(l) >= 25.5  <=>  max3x3(l) >= 0.1
__device__ __forceinline__ void elem(float p, float l, float vm,
                                     float& acc, float& accm) {
    float d    = fabsf(p - l);
    float m    = fminf(d, 0.5f);
    float relu = d - m;
    float asl  = 2.1f - l;
    float s    = ex2a(asl * lg2a(m));
    float u    = 1.0f + s;
    float la   = 0.6931471805599453f * lg2a(u);            // ln(1+s)
    float z    = fmaf(u, 0.7407407407407407f, -1.0f);
    float h    = fmaf(z, -1.4814814814814814f, 1.4814814814814814f);
    float t    = fmaf(z * z, h, h);                        // ~= 2/(1+s)
    float loss = fmaf((asl * s) * t, relu, la);
    acc += loss;
    if (vm >= 0.1f) accm += loss;
}

// Grid-stride over row PAIRS (r, r+1 within one image). 3x3 max is separable;
// the shared middle term max(l[r], l[r+1]) serves both rows' vertical maxes.
// 6 float4 loads per 2 rows; neighbor re-reads hit L2/L1.
// (R9: forcing 7 blocks/SM spills at 32 regs and regresses hard — (256,6) at
// 40 regs / 48 warps/SM is the measured spill-free optimum.)
__global__ void __launch_bounds__(256, 6)
awing(const float* __restrict__ pred, const float* __restrict__ lmk,
      float* __restrict__ out) {
    const int  lane = threadIdx.x & 31;
    const int  wid  = threadIdx.x >> 5;
    const int  gw   = blockIdx.x * WARPS + wid;
    const bool la0  = (lane == 0), la31 = (lane == 31);

    const float4* lp4 = reinterpret_cast<const float4*>(lmk);
    const float4* pp4 = reinterpret_cast<const float4*>(pred);

    float acc = 0.0f, accm = 0.0f;

#pragma unroll 1
    for (int pair = gw; pair < TOTAL_PAIRS; pair += NWARPS) {
        const int r  = (pair & 63) * 2;             // even row within image
        const int f0 = pair * 64 + lane;            // float4 idx of row r
        const int f1 = f0 + 32;                     // row r+1
        const int fu = (r == 0)   ? f0 : f0 - 32;   // row r-1 (SAME padding)
        const int fd = (r == 126) ? f1 : f1 + 32;   // row r+2 (SAME padding)

        float4 lu = lp4[fu];
        float4 l0 = lp4[f0];
        float4 l1 = lp4[f1];
        float4 ld = lp4[fd];
        float4 p0 = __ldcs(pp4 + f0);
        float4 p1 = __ldcs(pp4 + f1);

        float4 m01 = max4(l0, l1);                  // shared middle
        float4 ha  = hmax3(max4(lu, m01), la0, la31);   // 3x3 max, row r
        float4 hb  = hmax3(max4(m01, ld), la0, la31);   // 3x3 max, row r+1

        elem(p0.x, l0.x, ha.x, acc, accm);
        elem(p0.y, l0.y, ha.y, acc, accm);
        elem(p0.z, l0.z, ha.z, acc, accm);
        elem(p0.w, l0.w, ha.w, acc, accm);
        elem(p1.x, l1.x, hb.x, acc, accm);
        elem(p1.y, l1.y, hb.y, acc, accm);
        elem(p1.z, l1.z, hb.z, acc, accm);
        elem(p1.w, l1.w, hb.w, acc, accm);
    }

    float tot = fmaf(accm, 10.0f, acc) * 14.0f;
#pragma unroll
    for (int o = 16; o; o >>= 1)
        tot += __shfl_xor_sync(0xffffffffu, tot, o);

    __shared__ float  wsum[WARPS];
    __shared__ double sh[256];
    __shared__ bool   isLast;
    if (lane == 0) wsum[wid] = tot;
    __syncthreads();
    if (threadIdx.x == 0) {
        double s = 0.0;
#pragma unroll
        for (int i = 0; i < WARPS; ++i) s += (double)wsum[i];
        g_part[blockIdx.x] = s;
        __threadfence();
        unsigned int old = atomicAdd(&g_count, 1u);
        isLast = (old == (unsigned)(NBLK - 1));
        if (isLast) g_count = 0;             // reset for next graph replay
    }
    __syncthreads();

    if (isLast) {
        double s = 0.0;
        for (int i = threadIdx.x; i < NBLK; i += 256)
            s += __ldcg(&g_part[i]);
        sh[threadIdx.x] = s;
        __syncthreads();
#pragma unroll
        for (int k = 128; k; k >>= 1) {
            if (threadIdx.x < k) sh[threadIdx.x] += sh[threadIdx.x + k];
            __syncthreads();
        }
        if (threadIdx.x == 0)
            out[0] = (float)(sh[0] * (1.0 / TOTAL_ELEMS));
    }
}

extern "C" void kernel_launch(void* const* d_in, const int* in_sizes, int n_in,
                              void* d_out, int out_size) {
    const float* pred = (const float*)d_in[0];
    const float* lmk  = (const float*)d_in[1];
    awing<<<NBLK, 256>>>(pred, lmk, (float*)d_out);
}

// round 11
// speedup vs baseline: 1.3046x; 1.0035x over previous
#include <cuda_runtime.h>
#include <cstdint>

// Shape fixed by dataset: (64, 68, 128, 128) fp32 x2.
static constexpr int IMG_ROWS    = 128;
static constexpr int TOTAL_PAIRS = 64 * 68 * (IMG_ROWS / 2);  // 278528 row-pairs
static constexpr int WARPS       = 8;
static constexpr int NBLK        = 888;                 // 148 SMs x 6 blocks, one wave
static constexpr int NWARPS      = NBLK * WARPS;        // 7104 grid-stride warps
static constexpr double TOTAL_ELEMS = 71303168.0;

__device__ double       g_part[NBLK];
__device__ unsigned int g_count = 0;             // self-resetting each launch

__device__ __forceinline__ float ex2a(float x) {
    float y; asm("ex2.approx.f32 %0, %1;" : "=f"(y) : "f"(x)); return y;
}
__device__ __forceinline__ float lg2a(float x) {
    float y; asm("lg2.approx.f32 %0, %1;" : "=f"(y) : "f"(x)); return y;
}

__device__ __forceinline__ float4 max4(float4 a, float4 b) {
    return make_float4(fmaxf(a.x, b.x), fmaxf(a.y, b.y),
                       fmaxf(a.z, b.z), fmaxf(a.w, b.w));
}

// Horizontal 3-max with SAME padding (edge lanes use clipped window).
__device__ __forceinline__ float4 hmax3(float4 v, bool la0, bool la31) {
    float left  = __shfl_up_sync(0xffffffffu, v.w, 1);
    float right = __shfl_down_sync(0xffffffffu, v.x, 1);
    float m01 = fmaxf(v.x, v.y);
    float m12 = fmaxf(v.y, v.z);
    float m23 = fmaxf(v.z, v.w);
    float4 h;
    h.x = la0  ? m01 : fmaxf(left, m01);
    h.y = fmaxf(v.x, m12);
    h.z = fmaxf(v.y, m23);
    h.w = la31 ? m23 : fmaxf(m23, right);
    return h;
}

// Exact rewrite of reference (scaled by 1/14, x14 applied at warp level):
//   loss14 = ln(1+s) + [2*asl*s/(1+s)] * relu
//   s = min(d,0.5)^asl, relu = d - min(d,0.5), asl = 2.1 - l
//   2/(1+s) ~= 1.4815*(1-z)(1+z^2), z = (1+s)/1.35 - 1  (rel err <= 5.6e-5 on
//   the relu-active range s in (0.233,0.467); elsewhere relu == 0).
//   (R8: MUFU rcp here regresses — 4th MUFU + serial dependency; series ops
//   are independent FMA-pipe work that overlaps. Keep the series.)
//   mask: 255*max3x3(l) >= 25.5  <=>  max3x3(l) >= 0.1
__device__ __forceinline__ void elem(float p, float l, float vm,
                                     float& acc, float& accm) {
    float d    = fabsf(p - l);
    float m    = fminf(d, 0.5f);
    float relu = d - m;
    float asl  = 2.1f - l;
    float s    = ex2a(asl * lg2a(m));
    float u    = 1.0f + s;
    float la   = 0.6931471805599453f * lg2a(u);            // ln(1+s)
    float z    = fmaf(u, 0.7407407407407407f, -1.0f);
    float h    = fmaf(z, -1.4814814814814814f, 1.4814814814814814f);
    float t    = fmaf(z * z, h, h);                        // ~= 2/(1+s)
    float loss = fmaf((asl * s) * t, relu, la);
    acc += loss;
    if (vm >= 0.1f) accm += loss;
}

// Grid-stride over row PAIRS (r, r+1 within one image). 3x3 max is separable;
// the shared middle term max(l[r], l[r+1]) serves both rows' vertical maxes.
// 6 float4 loads per 2 rows; neighbor re-reads hit L2/L1.
// Measured optima (do not revisit): (256,6)/888 blocks = single wave at 48
// warps/SM spill-free (R9: 7 blocks spills); series > rcp (R8); pred stream
// uncached-last-use; landmark default-cached for halo reuse.
__global__ void __launch_bounds__(256, 6)
awing(const float* __restrict__ pred, const float* __restrict__ lmk,
      float* __restrict__ out) {
    const int  lane = threadIdx.x & 31;
    const int  wid  = threadIdx.x >> 5;
    const int  gw   = blockIdx.x * WARPS + wid;
    const bool la0  = (lane == 0), la31 = (lane == 31);

    const float4* lp4 = reinterpret_cast<const float4*>(lmk);
    const float4* pp4 = reinterpret_cast<const float4*>(pred);

    float acc = 0.0f, accm = 0.0f;

#pragma unroll 1
    for (int pair = gw; pair < TOTAL_PAIRS; pair += NWARPS) {
        const int r  = (pair & 63) * 2;             // even row within image
        const int f0 = pair * 64 + lane;            // float4 idx of row r
        const int f1 = f0 + 32;                     // row r+1
        const int fu = (r == 0)   ? f0 : f0 - 32;   // row r-1 (SAME padding)
        const int fd = (r == 126) ? f1 : f1 + 32;   // row r+2 (SAME padding)

        float4 lu = lp4[fu];
        float4 l0 = lp4[f0];
        float4 l1 = lp4[f1];
        float4 ld = lp4[fd];
        float4 p0 = __ldlu(pp4 + f0);               // read-once: last-use hint
        float4 p1 = __ldlu(pp4 + f1);

        float4 m01 = max4(l0, l1);                  // shared middle
        float4 ha  = hmax3(max4(lu, m01), la0, la31);   // 3x3 max, row r
        float4 hb  = hmax3(max4(m01, ld), la0, la31);   // 3x3 max, row r+1

        elem(p0.x, l0.x, ha.x, acc, accm);
        elem(p0.y, l0.y, ha.y, acc, accm);
        elem(p0.z, l0.z, ha.z, acc, accm);
        elem(p0.w, l0.w, ha.w, acc, accm);
        elem(p1.x, l1.x, hb.x, acc, accm);
        elem(p1.y, l1.y, hb.y, acc, accm);
        elem(p1.z, l1.z, hb.z, acc, accm);
        elem(p1.w, l1.w, hb.w, acc, accm);
    }

    float tot = fmaf(accm, 10.0f, acc) * 14.0f;
#pragma unroll
    for (int o = 16; o; o >>= 1)
        tot += __shfl_xor_sync(0xffffffffu, tot, o);

    __shared__ float  wsum[WARPS];
    __shared__ double sh[256];
    __shared__ bool   isLast;
    if (lane == 0) wsum[wid] = tot;
    __syncthreads();
    if (threadIdx.x == 0) {
        double s = 0.0;
#pragma unroll
        for (int i = 0; i < WARPS; ++i) s += (double)wsum[i];
        g_part[blockIdx.x] = s;
        __threadfence();
        unsigned int old = atomicAdd(&g_count, 1u);
        isLast = (old == (unsigned)(NBLK - 1));
        if (isLast) g_count = 0;             // reset for next graph replay
    }
    __syncthreads();

    if (isLast) {
        double s = 0.0;
        for (int i = threadIdx.x; i < NBLK; i += 256)
            s += __ldcg(&g_part[i]);
        sh[threadIdx.x] = s;
        __syncthreads();
#pragma unroll
        for (int k = 128; k; k >>= 1) {
            if (threadIdx.x < k) sh[threadIdx.x] += sh[threadIdx.x + k];
            __syncthreads();
        }
        if (threadIdx.x == 0)
            out[0] = (float)(sh[0] * (1.0 / TOTAL_ELEMS));
    }
}

extern "C" void kernel_launch(void* const* d_in, const int* in_sizes, int n_in,
                              void* d_out, int out_size) {
    const float* pred = (const float*)d_in[0];
    const float* lmk  = (const float*)d_in[1];
    awing<<<NBLK, 256>>>(pred, lmk, (float*)d_out);
}